// round 3
// baseline (speedup 1.0000x reference)
#include <cuda_runtime.h>

#define NN 50000
#define EE 500000
#define SD 128
#define HID 64
#define DEPTH 4
#define CUTF 5.0f
#define PI_F 3.14159265358979f

#define TE 64
#define NT_E ((EE + TE - 1) / TE)
#define TN 64
#define NT_N ((NN + TN - 1) / TN)

// ---------------- device scratch (no allocs allowed) ----------------
__device__ float g_sbuf[NN * SD];
__device__ float g_vbuf[NN * 9];
__device__ float g_sagg[NN * SD];
__device__ float g_vagg[NN * 9];
__device__ float g_Pa[NN * HID];
__device__ float g_Pb[NN * HID];
__device__ float g_C[EE];
__device__ float g_cnt[NN];
__device__ float g_icnt[NN];

__device__ __forceinline__ float silu_f(float x) {
    return x / (1.0f + __expf(-x));
}

// ---------------- small kernels ----------------
__global__ void k_init(const float* __restrict__ s, const float* __restrict__ v) {
    int i = blockIdx.x * blockDim.x + threadIdx.x;
    int stride = gridDim.x * blockDim.x;
    for (int j = i; j < NN * SD; j += stride) g_sbuf[j] = s[j];
    for (int j = i; j < NN * 9; j += stride) g_vbuf[j] = v[j];
    for (int j = i; j < NN; j += stride) g_cnt[j] = 0.0f;
}

__global__ void k_edgepre(const int* __restrict__ ei, const float* __restrict__ d) {
    int e = blockIdx.x * blockDim.x + threadIdx.x;
    if (e < EE) {
        float dd = d[e];
        float c = (dd < CUTF) ? 0.5f * (cosf(PI_F * dd / CUTF) + 1.0f) : 0.0f;
        g_C[e] = c;
        atomicAdd(&g_cnt[ei[e]], 1.0f);
    }
}

__global__ void k_inv() {
    int n = blockIdx.x * blockDim.x + threadIdx.x;
    if (n < NN) g_icnt[n] = 1.0f / fmaxf(g_cnt[n], 1.0f);
}

__global__ void k_zero() {
    int i = blockIdx.x * blockDim.x + threadIdx.x;
    int stride = gridDim.x * blockDim.x;
    for (int j = i; j < NN * SD; j += stride) g_sagg[j] = 0.0f;
    for (int j = i; j < NN * 9; j += stride) g_vagg[j] = 0.0f;
}

__global__ void k_vupd() {
    int i = blockIdx.x * blockDim.x + threadIdx.x;
    if (i < NN * 9) {
        int n = i / 9;
        g_vbuf[i] += g_vagg[i] * g_icnt[n];
    }
}

__global__ void k_out(float* __restrict__ out) {
    int i = blockIdx.x * blockDim.x + threadIdx.x;
    int stride = gridDim.x * blockDim.x;
    for (int j = i; j < NN * SD; j += stride) out[j] = g_sbuf[j];
    for (int j = i; j < NN * 9; j += stride) out[NN * SD + j] = g_vbuf[j];
}

// ---------------- projection kernel: Pa = S @ W1[0:128], Pb = S @ W1[128:256] ----------------
#define P_W 0
#define P_X (P_W + 128 * 128)           // 16384
#define P_TOT (P_X + 128 * 68)          // 25088 floats = 100352 B

__global__ void __launch_bounds__(256, 2) k_proj(const float* __restrict__ W1) {
    extern __shared__ float sm[];
    float* Ws = sm + P_W;   // [128k][128o'] o'<64 -> W1[k][o'], else W1[128+k][o'-64]
    float* Xt = sm + P_X;   // [128][68]

    const int tid = threadIdx.x;
    for (int i = tid; i < 128 * 128; i += 256) {
        int k = i >> 7, o = i & 127;
        Ws[i] = (o < 64) ? W1[k * 64 + o] : W1[(128 + k) * 64 + (o - 64)];
    }
    __syncthreads();

    const int wid = tid >> 5, lane = tid & 31;
    const int base = blockIdx.x * TN;
    const int nNd = min(TN, NN - base);

    for (int ii = wid; ii < TN; ii += 8) {
        const int n = base + ii;
        const bool valid = (ii < nNd);
        const float4* sp = (const float4*)&g_sbuf[(valid ? n : 0) * SD];
        float4 x = sp[lane];
        int k = lane * 4;
        Xt[k * 68 + ii] = x.x;
        Xt[(k + 1) * 68 + ii] = x.y;
        Xt[(k + 2) * 68 + ii] = x.z;
        Xt[(k + 3) * 68 + ii] = x.w;
    }
    __syncthreads();

    const int ox = (tid & 15) * 8;
    const int ey = (tid >> 4) * 4;
    float acc[4][8];
    #pragma unroll
    for (int i = 0; i < 4; i++)
        #pragma unroll
        for (int j = 0; j < 8; j++) acc[i][j] = 0.0f;
    #pragma unroll 4
    for (int k = 0; k < 128; k++) {
        float4 wa = *(const float4*)(Ws + k * 128 + ox);
        float4 wb = *(const float4*)(Ws + k * 128 + ox + 4);
        float4 x = *(const float4*)(Xt + k * 68 + ey);
        acc[0][0] += x.x * wa.x; acc[0][1] += x.x * wa.y; acc[0][2] += x.x * wa.z; acc[0][3] += x.x * wa.w;
        acc[0][4] += x.x * wb.x; acc[0][5] += x.x * wb.y; acc[0][6] += x.x * wb.z; acc[0][7] += x.x * wb.w;
        acc[1][0] += x.y * wa.x; acc[1][1] += x.y * wa.y; acc[1][2] += x.y * wa.z; acc[1][3] += x.y * wa.w;
        acc[1][4] += x.y * wb.x; acc[1][5] += x.y * wb.y; acc[1][6] += x.y * wb.z; acc[1][7] += x.y * wb.w;
        acc[2][0] += x.z * wa.x; acc[2][1] += x.z * wa.y; acc[2][2] += x.z * wa.z; acc[2][3] += x.z * wa.w;
        acc[2][4] += x.z * wb.x; acc[2][5] += x.z * wb.y; acc[2][6] += x.z * wb.z; acc[2][7] += x.z * wb.w;
        acc[3][0] += x.w * wa.x; acc[3][1] += x.w * wa.y; acc[3][2] += x.w * wa.z; acc[3][3] += x.w * wa.w;
        acc[3][4] += x.w * wb.x; acc[3][5] += x.w * wb.y; acc[3][6] += x.w * wb.z; acc[3][7] += x.w * wb.w;
    }
    float* dstbuf = (ox < 64) ? g_Pa : g_Pb;
    const int o0 = (ox < 64) ? ox : ox - 64;
    #pragma unroll
    for (int i = 0; i < 4; i++) {
        const int n = base + ey + i;
        if (ey + i < nNd) {
            float* p = &dstbuf[n * HID + o0];
            *(float4*)(p) = make_float4(acc[i][0], acc[i][1], acc[i][2], acc[i][3]);
            *(float4*)(p + 4) = make_float4(acc[i][4], acc[i][5], acc[i][6], acc[i][7]);
        }
    }
}

// ---------------- edge kernel ----------------
#define E_W2 0
#define E_B2 (E_W2 + 64 * 64)           // 4096
#define E_W3 (E_B2 + 64)                // 4160
#define E_B3 (E_W3 + 64 * 136)          // 12864
#define E_W1D (E_B3 + 136)              // 13000
#define E_B1 (E_W1D + 64)               // 13064
#define E_H1 (E_B1 + 64)                // 13128
#define E_H2 (E_H1 + 64 * 68)           // 17480
#define E_CS (E_H2 + 64 * 68)           // 21832
#define E_DS (E_CS + 64)
#define E_SS (E_DS + 64)
#define E_TOT (E_SS + 64)               // 22024 floats = 88096 B

__global__ void __launch_bounds__(256, 2) k_edge(
    const int* __restrict__ ei, const float* __restrict__ darr,
    const float* __restrict__ rarr,
    const float* __restrict__ W1, const float* __restrict__ b1,
    const float* __restrict__ W2, const float* __restrict__ b2,
    const float* __restrict__ W3, const float* __restrict__ b3)
{
    extern __shared__ float sm[];
    float* W2s = sm + E_W2;
    float* b2s = sm + E_B2;
    float* W3s = sm + E_W3;
    float* b3s = sm + E_B3;
    float* w1d = sm + E_W1D;
    float* b1s = sm + E_B1;
    float* H1  = sm + E_H1;   // [64][68]
    float* H2  = sm + E_H2;   // [64][68]
    float* CS  = sm + E_CS;
    int*   dstS = (int*)(sm + E_DS);
    int*   srcS = (int*)(sm + E_SS);

    const int tid = threadIdx.x;

    for (int i = tid; i < 64 * 64; i += 256) W2s[i] = W2[i];
    for (int i = tid; i < 64 * 134; i += 256) {
        int k = i / 134, o = i % 134;
        W3s[k * 136 + o] = W3[i];
    }
    if (tid < 64) {
        b1s[tid] = b1[tid];
        b2s[tid] = b2[tid];
        w1d[tid] = W1[256 * 64 + tid];   // last row of W1 (d coefficient)
    }
    for (int i = tid; i < 134; i += 256) b3s[i] = b3[i];
    __syncthreads();

    const int wid = tid >> 5, lane = tid & 31;

    for (int tile = blockIdx.x; tile < NT_E; tile += gridDim.x) {
        const int base = tile * TE;
        const int nE = min(TE, EE - base);

        // ---- gather + fused GEMM1 (now just adds) -> silu -> H1 [k][e] ----
        for (int ee = wid; ee < TE; ee += 8) {
            const int e = base + ee;
            const bool valid = (ee < nE);
            int dst = 0, src = 0;
            float dd = 0.0f;
            if (valid) { dst = ei[e]; src = ei[EE + e]; dd = darr[e]; }
            const float2 a = ((const float2*)&g_Pa[dst * HID])[lane];
            const float2 b = ((const float2*)&g_Pb[src * HID])[lane];
            const int k0 = lane * 2;
            float h0 = a.x + b.x + dd * w1d[k0] + b1s[k0];
            float h1 = a.y + b.y + dd * w1d[k0 + 1] + b1s[k0 + 1];
            H1[k0 * 68 + ee]       = valid ? silu_f(h0) : 0.0f;
            H1[(k0 + 1) * 68 + ee] = valid ? silu_f(h1) : 0.0f;
            if (lane == 0) {
                CS[ee] = valid ? g_C[e] : 0.0f;
                dstS[ee] = dst; srcS[ee] = src;
            }
        }
        __syncthreads();

        // ---- GEMM2: [64e x 64] @ [64 x 64] -> silu -> H2 ----
        {
            const int ox = (tid & 15) * 4;
            const int ey = (tid >> 4) * 4;
            float acc[4][4];
            #pragma unroll
            for (int j = 0; j < 4; j++) {
                float b = b2s[ox + j];
                acc[0][j] = b; acc[1][j] = b; acc[2][j] = b; acc[3][j] = b;
            }
            #pragma unroll 4
            for (int k = 0; k < 64; k++) {
                float4 w = *(const float4*)(W2s + k * 64 + ox);
                float4 x = *(const float4*)(H1 + k * 68 + ey);
                acc[0][0] += x.x * w.x; acc[0][1] += x.x * w.y; acc[0][2] += x.x * w.z; acc[0][3] += x.x * w.w;
                acc[1][0] += x.y * w.x; acc[1][1] += x.y * w.y; acc[1][2] += x.y * w.z; acc[1][3] += x.y * w.w;
                acc[2][0] += x.z * w.x; acc[2][1] += x.z * w.y; acc[2][2] += x.z * w.z; acc[2][3] += x.z * w.w;
                acc[3][0] += x.w * w.x; acc[3][1] += x.w * w.y; acc[3][2] += x.w * w.z; acc[3][3] += x.w * w.w;
            }
            #pragma unroll
            for (int j = 0; j < 4; j++)
                #pragma unroll
                for (int i = 0; i < 4; i++)
                    H2[(ox + j) * 68 + ey + i] = silu_f(acc[i][j]);
        }
        __syncthreads();

        // ---- GEMM3 scalar part: [64e x 64] @ [64 x 128], fused scatter ----
        {
            const int ox = (tid & 15) * 8;
            const int ey = (tid >> 4) * 4;
            float acc[4][8];
            #pragma unroll
            for (int j = 0; j < 8; j++) {
                float b = b3s[ox + j];
                acc[0][j] = b; acc[1][j] = b; acc[2][j] = b; acc[3][j] = b;
            }
            #pragma unroll 4
            for (int k = 0; k < 64; k++) {
                float4 wa = *(const float4*)(W3s + k * 136 + ox);
                float4 wb = *(const float4*)(W3s + k * 136 + ox + 4);
                float4 x = *(const float4*)(H2 + k * 68 + ey);
                acc[0][0] += x.x * wa.x; acc[0][1] += x.x * wa.y; acc[0][2] += x.x * wa.z; acc[0][3] += x.x * wa.w;
                acc[0][4] += x.x * wb.x; acc[0][5] += x.x * wb.y; acc[0][6] += x.x * wb.z; acc[0][7] += x.x * wb.w;
                acc[1][0] += x.y * wa.x; acc[1][1] += x.y * wa.y; acc[1][2] += x.y * wa.z; acc[1][3] += x.y * wa.w;
                acc[1][4] += x.y * wb.x; acc[1][5] += x.y * wb.y; acc[1][6] += x.y * wb.z; acc[1][7] += x.y * wb.w;
                acc[2][0] += x.z * wa.x; acc[2][1] += x.z * wa.y; acc[2][2] += x.z * wa.z; acc[2][3] += x.z * wa.w;
                acc[2][4] += x.z * wb.x; acc[2][5] += x.z * wb.y; acc[2][6] += x.z * wb.z; acc[2][7] += x.z * wb.w;
                acc[3][0] += x.w * wa.x; acc[3][1] += x.w * wa.y; acc[3][2] += x.w * wa.z; acc[3][3] += x.w * wa.w;
                acc[3][4] += x.w * wb.x; acc[3][5] += x.w * wb.y; acc[3][6] += x.w * wb.z; acc[3][7] += x.w * wb.w;
            }
            #pragma unroll
            for (int i = 0; i < 4; i++) {
                const int ee = ey + i;
                if (ee < nE) {
                    const float c = CS[ee];
                    float* dp = &g_sagg[dstS[ee] * SD + ox];
                    #pragma unroll
                    for (int j = 0; j < 8; j++) atomicAdd(&dp[j], acc[i][j] * c);
                }
            }
        }

        // ---- GEMM3 vector gates (6 outputs) + vector scatter ----
        if (tid < TE) {
            const int ee = tid;
            if (ee < nE) {
                float a[6];
                #pragma unroll
                for (int j = 0; j < 6; j++) a[j] = b3s[128 + j];
                #pragma unroll 4
                for (int k = 0; k < 64; k++) {
                    float x = H2[k * 68 + ee];
                    #pragma unroll
                    for (int j = 0; j < 6; j++) a[j] += x * W3s[k * 136 + 128 + j];
                }
                const float c = CS[ee];
                const int dst = dstS[ee], src = srcS[ee];
                const int e = base + ee;
                float rv[3];
                #pragma unroll
                for (int x = 0; x < 3; x++) rv[x] = rarr[e * 3 + x];
                #pragma unroll
                for (int vi = 0; vi < 3; vi++) {
                    const float gv = a[vi], gr = a[3 + vi];
                    #pragma unroll
                    for (int x = 0; x < 3; x++) {
                        float val = (g_vbuf[src * 9 + vi * 3 + x] * gv + rv[x] * gr) * c;
                        atomicAdd(&g_vagg[dst * 9 + vi * 3 + x], val);
                    }
                }
            }
        }
        __syncthreads();
    }
}

// ---------------- node kernel ----------------
#define N_W1 0
#define N_B1 (256 * 64)                 // 16384
#define N_W2 (N_B1 + 64)                // 16448
#define N_B2 (N_W2 + 64 * 128)          // 24640
#define N_XT (N_B2 + 128)               // 24768
#define N_UT (N_XT + 256 * 68)          // 42176
#define N_TOT (N_UT + 64 * 68)          // 46528 floats = 186112 B

__global__ void __launch_bounds__(256, 1) k_node(
    const float* __restrict__ Wn1, const float* __restrict__ bn1,
    const float* __restrict__ Wn2, const float* __restrict__ bn2)
{
    extern __shared__ float sm[];
    float* W1s = sm + N_W1;
    float* b1s = sm + N_B1;
    float* W2s = sm + N_W2;
    float* b2s = sm + N_B2;
    float* Xt  = sm + N_XT;   // [256][68]
    float* Ut  = sm + N_UT;   // [64][68]

    const int tid = threadIdx.x;
    for (int i = tid; i < 256 * 64; i += 256) W1s[i] = Wn1[i];
    for (int i = tid; i < 64 * 128; i += 256) W2s[i] = Wn2[i];
    if (tid < 64) b1s[tid] = bn1[tid];
    if (tid < 128) b2s[tid] = bn2[tid];
    __syncthreads();

    const int wid = tid >> 5, lane = tid & 31;

    for (int tile = blockIdx.x; tile < NT_N; tile += gridDim.x) {
        const int base = tile * TN;
        const int nNd = min(TN, NN - base);

        for (int ii = wid; ii < TN; ii += 8) {
            const int n = base + ii;
            const bool valid = (ii < nNd);
            const float* sp = &g_sbuf[(valid ? n : 0) * SD];
            const float* ap = &g_sagg[(valid ? n : 0) * SD];
            #pragma unroll
            for (int k4 = 0; k4 < 4; k4++) {
                int k = lane + k4 * 32;
                Xt[k * 68 + ii]        = valid ? sp[k] : 0.0f;
                Xt[(SD + k) * 68 + ii] = valid ? ap[k] : 0.0f;
            }
        }
        __syncthreads();

        // GEMM1: [64n x 256] @ [256 x 64] -> silu -> Ut
        {
            const int ox = (tid & 15) * 4;
            const int ey = (tid >> 4) * 4;
            float acc[4][4];
            #pragma unroll
            for (int j = 0; j < 4; j++) {
                float b = b1s[ox + j];
                acc[0][j] = b; acc[1][j] = b; acc[2][j] = b; acc[3][j] = b;
            }
            #pragma unroll 4
            for (int k = 0; k < 256; k++) {
                float4 w = *(const float4*)(W1s + k * 64 + ox);
                float4 x = *(const float4*)(Xt + k * 68 + ey);
                acc[0][0] += x.x * w.x; acc[0][1] += x.x * w.y; acc[0][2] += x.x * w.z; acc[0][3] += x.x * w.w;
                acc[1][0] += x.y * w.x; acc[1][1] += x.y * w.y; acc[1][2] += x.y * w.z; acc[1][3] += x.y * w.w;
                acc[2][0] += x.z * w.x; acc[2][1] += x.z * w.y; acc[2][2] += x.z * w.z; acc[2][3] += x.z * w.w;
                acc[3][0] += x.w * w.x; acc[3][1] += x.w * w.y; acc[3][2] += x.w * w.z; acc[3][3] += x.w * w.w;
            }
            #pragma unroll
            for (int j = 0; j < 4; j++)
                #pragma unroll
                for (int i = 0; i < 4; i++)
                    Ut[(ox + j) * 68 + ey + i] = silu_f(acc[i][j]);
        }
        __syncthreads();

        // GEMM2: [64n x 64] @ [64 x 128] -> s += .
        {
            const int ox = (tid & 15) * 8;
            const int ey = (tid >> 4) * 4;
            float acc[4][8];
            #pragma unroll
            for (int j = 0; j < 8; j++) {
                float b = b2s[ox + j];
                acc[0][j] = b; acc[1][j] = b; acc[2][j] = b; acc[3][j] = b;
            }
            #pragma unroll 4
            for (int k = 0; k < 64; k++) {
                float4 wa = *(const float4*)(W2s + k * 128 + ox);
                float4 wb = *(const float4*)(W2s + k * 128 + ox + 4);
                float4 x = *(const float4*)(Ut + k * 68 + ey);
                acc[0][0] += x.x * wa.x; acc[0][1] += x.x * wa.y; acc[0][2] += x.x * wa.z; acc[0][3] += x.x * wa.w;
                acc[0][4] += x.x * wb.x; acc[0][5] += x.x * wb.y; acc[0][6] += x.x * wb.z; acc[0][7] += x.x * wb.w;
                acc[1][0] += x.y * wa.x; acc[1][1] += x.y * wa.y; acc[1][2] += x.y * wa.z; acc[1][3] += x.y * wa.w;
                acc[1][4] += x.y * wb.x; acc[1][5] += x.y * wb.y; acc[1][6] += x.y * wb.z; acc[1][7] += x.y * wb.w;
                acc[2][0] += x.z * wa.x; acc[2][1] += x.z * wa.y; acc[2][2] += x.z * wa.z; acc[2][3] += x.z * wa.w;
                acc[2][4] += x.z * wb.x; acc[2][5] += x.z * wb.y; acc[2][6] += x.z * wb.z; acc[2][7] += x.z * wb.w;
                acc[3][0] += x.w * wa.x; acc[3][1] += x.w * wa.y; acc[3][2] += x.w * wa.z; acc[3][3] += x.w * wa.w;
                acc[3][4] += x.w * wb.x; acc[3][5] += x.w * wb.y; acc[3][6] += x.w * wb.z; acc[3][7] += x.w * wb.w;
            }
            #pragma unroll
            for (int i = 0; i < 4; i++) {
                const int n = base + ey + i;
                if (ey + i < nNd) {
                    float* sp = &g_sbuf[n * SD + ox];
                    #pragma unroll
                    for (int j = 0; j < 8; j++) sp[j] += acc[i][j];
                }
            }
        }
        __syncthreads();
    }
}

// ---------------- host launch ----------------
extern "C" void kernel_launch(void* const* d_in, const int* in_sizes, int n_in,
                              void* d_out, int out_size) {
    const float* s   = (const float*)d_in[0];
    const float* v   = (const float*)d_in[1];
    const int*   ei  = (const int*)d_in[2];
    const float* d   = (const float*)d_in[3];
    const float* r   = (const float*)d_in[4];
    const float* W1  = (const float*)d_in[5];
    const float* b1  = (const float*)d_in[6];
    const float* W2  = (const float*)d_in[7];
    const float* b2  = (const float*)d_in[8];
    const float* W3  = (const float*)d_in[9];
    const float* b3  = (const float*)d_in[10];
    const float* Wn1 = (const float*)d_in[11];
    const float* bn1 = (const float*)d_in[12];
    const float* Wn2 = (const float*)d_in[13];
    const float* bn2 = (const float*)d_in[14];
    float* out = (float*)d_out;

    const int psm = P_TOT * 4;
    const int esm = E_TOT * 4;
    const int nsm = N_TOT * 4;
    cudaFuncSetAttribute(k_proj, cudaFuncAttributeMaxDynamicSharedMemorySize, psm);
    cudaFuncSetAttribute(k_edge, cudaFuncAttributeMaxDynamicSharedMemorySize, esm);
    cudaFuncSetAttribute(k_node, cudaFuncAttributeMaxDynamicSharedMemorySize, nsm);

    k_init<<<1024, 256>>>(s, v);
    k_edgepre<<<(EE + 255) / 256, 256>>>(ei, d);
    k_inv<<<(NN + 255) / 256, 256>>>();

    for (int l = 0; l < DEPTH; l++) {
        k_zero<<<1024, 256>>>();
        k_proj<<<NT_N, 256, psm>>>(W1 + l * 257 * 64);
        k_edge<<<304, 256, esm>>>(ei, d, r,
                                  W1 + l * 257 * 64, b1 + l * 64,
                                  W2 + l * 64 * 64, b2 + l * 64,
                                  W3 + l * 64 * 134, b3 + l * 134);
        k_node<<<152, 256, nsm>>>(Wn1 + l * 256 * 64, bn1 + l * 64,
                                  Wn2 + l * 64 * 128, bn2 + l * 128);
        k_vupd<<<(NN * 9 + 255) / 256, 256>>>();
    }
    k_out<<<1024, 256>>>(out);
}

// round 4
// speedup vs baseline: 2.1367x; 2.1367x over previous
#include <cuda_runtime.h>

#define NN 50000
#define EE 500000
#define SD 128
#define HID 64
#define DEPTH 4
#define CUTF 5.0f
#define PI_F 3.14159265358979f

#define TE 64
#define NT_E ((EE + TE - 1) / TE)
#define TN 64
#define NT_N ((NN + TN - 1) / TN)

// ---------------- device scratch (no allocs allowed) ----------------
__device__ float g_sbuf[NN * SD];
__device__ float g_vbuf[NN * 9];
__device__ float g_sagg[NN * SD];
__device__ float g_vagg[NN * 9];
__device__ float g_Pa[NN * HID];
__device__ float g_Pb[NN * HID];
__device__ float g_icnt[NN];
__device__ int   g_cnti[NN];
__device__ int   g_cur[NN];
// dst-sorted edge data
__device__ int   g_dstS[EE];
__device__ int   g_srcS[EE];
__device__ float g_Cs[EE];
__device__ float g_dsrt[EE];
__device__ float g_rs[EE * 3];

__device__ __forceinline__ float silu_f(float x) {
    return x / (1.0f + __expf(-x));
}

// ---------------- small kernels ----------------
__global__ void k_init(const float* __restrict__ s, const float* __restrict__ v) {
    int i = blockIdx.x * blockDim.x + threadIdx.x;
    int stride = gridDim.x * blockDim.x;
    for (int j = i; j < NN * SD; j += stride) g_sbuf[j] = s[j];
    for (int j = i; j < NN * 9; j += stride) g_vbuf[j] = v[j];
    for (int j = i; j < NN; j += stride) g_cnti[j] = 0;
}

__global__ void k_cnt(const int* __restrict__ ei) {
    int e = blockIdx.x * blockDim.x + threadIdx.x;
    if (e < EE) atomicAdd(&g_cnti[ei[e]], 1);
}

// single-block exclusive scan: g_cur[i] = sum_{j<i} cnt[j]; also icnt
__global__ void k_scan() {
    __shared__ int sh[1024];
    __shared__ int carry;
    int tid = threadIdx.x;
    if (tid == 0) carry = 0;
    __syncthreads();
    for (int base = 0; base < NN; base += 1024) {
        int i = base + tid;
        int x = (i < NN) ? g_cnti[i] : 0;
        sh[tid] = x;
        __syncthreads();
        for (int off = 1; off < 1024; off <<= 1) {
            int t = (tid >= off) ? sh[tid - off] : 0;
            __syncthreads();
            sh[tid] += t;
            __syncthreads();
        }
        if (i < NN) {
            g_cur[i] = carry + sh[tid] - x;   // exclusive
            g_icnt[i] = 1.0f / fmaxf((float)x, 1.0f);
        }
        __syncthreads();
        if (tid == 1023) carry += sh[1023];
        __syncthreads();
    }
}

__global__ void k_perm(const int* __restrict__ ei, const float* __restrict__ d,
                       const float* __restrict__ r) {
    int e = blockIdx.x * blockDim.x + threadIdx.x;
    if (e < EE) {
        int dst = ei[e];
        int pos = atomicAdd(&g_cur[dst], 1);
        g_dstS[pos] = dst;
        g_srcS[pos] = ei[EE + e];
        float dd = d[e];
        g_dsrt[pos] = dd;
        g_Cs[pos] = (dd < CUTF) ? 0.5f * (cosf(PI_F * dd / CUTF) + 1.0f) : 0.0f;
        g_rs[pos * 3 + 0] = r[e * 3 + 0];
        g_rs[pos * 3 + 1] = r[e * 3 + 1];
        g_rs[pos * 3 + 2] = r[e * 3 + 2];
    }
}

__global__ void k_zero() {
    int i = blockIdx.x * blockDim.x + threadIdx.x;
    int stride = gridDim.x * blockDim.x;
    for (int j = i; j < NN * SD; j += stride) g_sagg[j] = 0.0f;
    for (int j = i; j < NN * 9; j += stride) g_vagg[j] = 0.0f;
}

__global__ void k_vupd() {
    int i = blockIdx.x * blockDim.x + threadIdx.x;
    if (i < NN * 9) {
        int n = i / 9;
        g_vbuf[i] += g_vagg[i] * g_icnt[n];
    }
}

__global__ void k_out(float* __restrict__ out) {
    int i = blockIdx.x * blockDim.x + threadIdx.x;
    int stride = gridDim.x * blockDim.x;
    for (int j = i; j < NN * SD; j += stride) out[j] = g_sbuf[j];
    for (int j = i; j < NN * 9; j += stride) out[NN * SD + j] = g_vbuf[j];
}

// ---------------- projection kernel: Pa = S @ W1[0:128], Pb = S @ W1[128:256] ----------------
#define P_W 0
#define P_X (P_W + 128 * 128)
#define P_TOT (P_X + 128 * 68)

__global__ void __launch_bounds__(256, 2) k_proj(const float* __restrict__ W1) {
    extern __shared__ float sm[];
    float* Ws = sm + P_W;
    float* Xt = sm + P_X;

    const int tid = threadIdx.x;
    for (int i = tid; i < 128 * 128; i += 256) {
        int k = i >> 7, o = i & 127;
        Ws[i] = (o < 64) ? W1[k * 64 + o] : W1[(128 + k) * 64 + (o - 64)];
    }
    __syncthreads();

    const int wid = tid >> 5, lane = tid & 31;
    const int base = blockIdx.x * TN;
    const int nNd = min(TN, NN - base);

    for (int ii = wid; ii < TN; ii += 8) {
        const int n = base + ii;
        const bool valid = (ii < nNd);
        const float4* sp = (const float4*)&g_sbuf[(valid ? n : 0) * SD];
        float4 x = sp[lane];
        int k = lane * 4;
        Xt[k * 68 + ii] = x.x;
        Xt[(k + 1) * 68 + ii] = x.y;
        Xt[(k + 2) * 68 + ii] = x.z;
        Xt[(k + 3) * 68 + ii] = x.w;
    }
    __syncthreads();

    const int ox = (tid & 15) * 8;
    const int ey = (tid >> 4) * 4;
    float acc[4][8];
    #pragma unroll
    for (int i = 0; i < 4; i++)
        #pragma unroll
        for (int j = 0; j < 8; j++) acc[i][j] = 0.0f;
    #pragma unroll 4
    for (int k = 0; k < 128; k++) {
        float4 wa = *(const float4*)(Ws + k * 128 + ox);
        float4 wb = *(const float4*)(Ws + k * 128 + ox + 4);
        float4 x = *(const float4*)(Xt + k * 68 + ey);
        acc[0][0] += x.x * wa.x; acc[0][1] += x.x * wa.y; acc[0][2] += x.x * wa.z; acc[0][3] += x.x * wa.w;
        acc[0][4] += x.x * wb.x; acc[0][5] += x.x * wb.y; acc[0][6] += x.x * wb.z; acc[0][7] += x.x * wb.w;
        acc[1][0] += x.y * wa.x; acc[1][1] += x.y * wa.y; acc[1][2] += x.y * wa.z; acc[1][3] += x.y * wa.w;
        acc[1][4] += x.y * wb.x; acc[1][5] += x.y * wb.y; acc[1][6] += x.y * wb.z; acc[1][7] += x.y * wb.w;
        acc[2][0] += x.z * wa.x; acc[2][1] += x.z * wa.y; acc[2][2] += x.z * wa.z; acc[2][3] += x.z * wa.w;
        acc[2][4] += x.z * wb.x; acc[2][5] += x.z * wb.y; acc[2][6] += x.z * wb.z; acc[2][7] += x.z * wb.w;
        acc[3][0] += x.w * wa.x; acc[3][1] += x.w * wa.y; acc[3][2] += x.w * wa.z; acc[3][3] += x.w * wa.w;
        acc[3][4] += x.w * wb.x; acc[3][5] += x.w * wb.y; acc[3][6] += x.w * wb.z; acc[3][7] += x.w * wb.w;
    }
    float* dstbuf = (ox < 64) ? g_Pa : g_Pb;
    const int o0 = (ox < 64) ? ox : ox - 64;
    #pragma unroll
    for (int i = 0; i < 4; i++) {
        const int n = base + ey + i;
        if (ey + i < nNd) {
            float* p = &dstbuf[n * HID + o0];
            *(float4*)(p) = make_float4(acc[i][0], acc[i][1], acc[i][2], acc[i][3]);
            *(float4*)(p + 4) = make_float4(acc[i][4], acc[i][5], acc[i][6], acc[i][7]);
        }
    }
}

// ---------------- edge kernel (dst-sorted) ----------------
#define E_W2 0
#define E_B2 (E_W2 + 64 * 64)           // 4096
#define E_W3 (E_B2 + 64)                // 4160
#define E_B3 (E_W3 + 64 * 136)          // 12864
#define E_W1D (E_B3 + 136)              // 13000
#define E_B1 (E_W1D + 64)               // 13064
#define E_H1 (E_B1 + 64)                // 13128
#define E_H2 (E_H1 + 64 * 68)           // 17480
#define E_VM (E_H2 + 64 * 68)           // 21832
#define E_CS (E_VM + 64 * 12)           // 22600
#define E_DS (E_CS + 64)
#define E_SS (E_DS + 64)
#define E_TOT (E_SS + 64)               // 22792 floats = 91168 B

__global__ void __launch_bounds__(256, 2) k_edge(
    const float* __restrict__ W1, const float* __restrict__ b1,
    const float* __restrict__ W2, const float* __restrict__ b2,
    const float* __restrict__ W3, const float* __restrict__ b3)
{
    extern __shared__ float sm[];
    float* W2s = sm + E_W2;
    float* b2s = sm + E_B2;
    float* W3s = sm + E_W3;
    float* b3s = sm + E_B3;
    float* w1d = sm + E_W1D;
    float* b1s = sm + E_B1;
    float* H1  = sm + E_H1;   // [64k][68]
    float* H2  = sm + E_H2;   // [64k][68]
    float* Vm  = sm + E_VM;   // [64e][12]
    float* CS  = sm + E_CS;
    int*   dstSh = (int*)(sm + E_DS);
    int*   srcSh = (int*)(sm + E_SS);

    const int tid = threadIdx.x;

    for (int i = tid; i < 64 * 64; i += 256) W2s[i] = W2[i];
    for (int i = tid; i < 64 * 134; i += 256) {
        int k = i / 134, o = i % 134;
        W3s[k * 136 + o] = W3[i];
    }
    if (tid < 64) {
        b1s[tid] = b1[tid];
        b2s[tid] = b2[tid];
        w1d[tid] = W1[256 * 64 + tid];
    }
    for (int i = tid; i < 134; i += 256) b3s[i] = b3[i];
    __syncthreads();

    const int wid = tid >> 5, lane = tid & 31;

    for (int tile = blockIdx.x; tile < NT_E; tile += gridDim.x) {
        const int base = tile * TE;
        const int nE = min(TE, EE - base);

        // ---- gather (sorted, coalesced) + silu -> H1 [k][e] ----
        for (int ee = wid; ee < TE; ee += 8) {
            const int epos = base + ee;
            const bool valid = (ee < nE);
            int dst = 0, src = 0;
            float dd = 0.0f;
            if (valid) { dst = g_dstS[epos]; src = g_srcS[epos]; dd = g_dsrt[epos]; }
            const float2 a = ((const float2*)&g_Pa[dst * HID])[lane];
            const float2 b = ((const float2*)&g_Pb[src * HID])[lane];
            const int k0 = lane * 2;
            float h0 = a.x + b.x + dd * w1d[k0] + b1s[k0];
            float h1 = a.y + b.y + dd * w1d[k0 + 1] + b1s[k0 + 1];
            H1[k0 * 68 + ee]       = valid ? silu_f(h0) : 0.0f;
            H1[(k0 + 1) * 68 + ee] = valid ? silu_f(h1) : 0.0f;
            if (lane == 0) {
                CS[ee] = valid ? g_Cs[epos] : 0.0f;
                dstSh[ee] = dst; srcSh[ee] = src;
            }
        }
        __syncthreads();

        // ---- GEMM2: [64e x 64] @ [64 x 64] -> silu -> H2 ----
        {
            const int ox = (tid & 15) * 4;
            const int ey = (tid >> 4) * 4;
            float acc[4][4];
            #pragma unroll
            for (int j = 0; j < 4; j++) {
                float b = b2s[ox + j];
                acc[0][j] = b; acc[1][j] = b; acc[2][j] = b; acc[3][j] = b;
            }
            #pragma unroll 4
            for (int k = 0; k < 64; k++) {
                float4 w = *(const float4*)(W2s + k * 64 + ox);
                float4 x = *(const float4*)(H1 + k * 68 + ey);
                acc[0][0] += x.x * w.x; acc[0][1] += x.x * w.y; acc[0][2] += x.x * w.z; acc[0][3] += x.x * w.w;
                acc[1][0] += x.y * w.x; acc[1][1] += x.y * w.y; acc[1][2] += x.y * w.z; acc[1][3] += x.y * w.w;
                acc[2][0] += x.z * w.x; acc[2][1] += x.z * w.y; acc[2][2] += x.z * w.z; acc[2][3] += x.z * w.w;
                acc[3][0] += x.w * w.x; acc[3][1] += x.w * w.y; acc[3][2] += x.w * w.z; acc[3][3] += x.w * w.w;
            }
            #pragma unroll
            for (int j = 0; j < 4; j++)
                #pragma unroll
                for (int i = 0; i < 4; i++)
                    H2[(ox + j) * 68 + ey + i] = silu_f(acc[i][j]);
        }
        __syncthreads();

        // ---- GEMM3 scalar: 8 edges x 4 cols per thread, run-reduced scatter ----
        {
            const int ox = (tid & 31) * 4;          // 0..124
            const int ey = (tid >> 5) * 8;          // 0..56
            float acc[8][4];
            #pragma unroll
            for (int i = 0; i < 8; i++) {
                acc[i][0] = b3s[ox]; acc[i][1] = b3s[ox + 1];
                acc[i][2] = b3s[ox + 2]; acc[i][3] = b3s[ox + 3];
            }
            #pragma unroll 4
            for (int k = 0; k < 64; k++) {
                float4 w  = *(const float4*)(W3s + k * 136 + ox);
                float4 xa = *(const float4*)(H2 + k * 68 + ey);
                float4 xb = *(const float4*)(H2 + k * 68 + ey + 4);
                acc[0][0] += xa.x * w.x; acc[0][1] += xa.x * w.y; acc[0][2] += xa.x * w.z; acc[0][3] += xa.x * w.w;
                acc[1][0] += xa.y * w.x; acc[1][1] += xa.y * w.y; acc[1][2] += xa.y * w.z; acc[1][3] += xa.y * w.w;
                acc[2][0] += xa.z * w.x; acc[2][1] += xa.z * w.y; acc[2][2] += xa.z * w.z; acc[2][3] += xa.z * w.w;
                acc[3][0] += xa.w * w.x; acc[3][1] += xa.w * w.y; acc[3][2] += xa.w * w.z; acc[3][3] += xa.w * w.w;
                acc[4][0] += xb.x * w.x; acc[4][1] += xb.x * w.y; acc[4][2] += xb.x * w.z; acc[4][3] += xb.x * w.w;
                acc[5][0] += xb.y * w.x; acc[5][1] += xb.y * w.y; acc[5][2] += xb.y * w.z; acc[5][3] += xb.y * w.w;
                acc[6][0] += xb.z * w.x; acc[6][1] += xb.z * w.y; acc[6][2] += xb.z * w.z; acc[6][3] += xb.z * w.w;
                acc[7][0] += xb.w * w.x; acc[7][1] += xb.w * w.y; acc[7][2] += xb.w * w.z; acc[7][3] += xb.w * w.w;
            }
            // run-detected flush over 8 consecutive sorted edges
            int cur = dstSh[ey];
            float s0 = 0.0f, s1 = 0.0f, s2 = 0.0f, s3 = 0.0f;
            #pragma unroll
            for (int i = 0; i < 8; i++) {
                int dd2 = dstSh[ey + i];
                if (dd2 != cur) {
                    float* p = &g_sagg[cur * SD + ox];
                    atomicAdd(p + 0, s0); atomicAdd(p + 1, s1);
                    atomicAdd(p + 2, s2); atomicAdd(p + 3, s3);
                    cur = dd2; s0 = s1 = s2 = s3 = 0.0f;
                }
                float c = CS[ey + i];
                s0 += acc[i][0] * c; s1 += acc[i][1] * c;
                s2 += acc[i][2] * c; s3 += acc[i][3] * c;
            }
            float* p = &g_sagg[cur * SD + ox];
            atomicAdd(p + 0, s0); atomicAdd(p + 1, s1);
            atomicAdd(p + 2, s2); atomicAdd(p + 3, s3);
        }

        // ---- vector gates -> Vm (per edge) ----
        if (tid < TE) {
            const int ee = tid;
            const int epos = base + ee;
            float a6[6];
            #pragma unroll
            for (int j = 0; j < 6; j++) a6[j] = b3s[128 + j];
            #pragma unroll 4
            for (int k = 0; k < 64; k++) {
                float x = H2[k * 68 + ee];
                #pragma unroll
                for (int j = 0; j < 6; j++) a6[j] += x * W3s[k * 136 + 128 + j];
            }
            const float c = CS[ee];
            const int src = srcSh[ee];
            float rv[3];
            #pragma unroll
            for (int x = 0; x < 3; x++) rv[x] = (epos < EE) ? g_rs[epos * 3 + x] : 0.0f;
            #pragma unroll
            for (int vi = 0; vi < 3; vi++) {
                const float gv = a6[vi], gr = a6[3 + vi];
                #pragma unroll
                for (int x = 0; x < 3; x++)
                    Vm[ee * 12 + vi * 3 + x] =
                        (g_vbuf[src * 9 + vi * 3 + x] * gv + rv[x] * gr) * c;
            }
        }
        __syncthreads();

        // ---- group-reduce Vm -> v_agg ----
        if (tid < 36) {
            const int col = tid % 9, seg = tid / 9;
            const int e0 = seg * 16;
            int cur = dstSh[e0];
            float sum = 0.0f;
            #pragma unroll 4
            for (int i = 0; i < 16; i++) {
                int ee = e0 + i;
                int dd2 = dstSh[ee];
                if (dd2 != cur) {
                    atomicAdd(&g_vagg[cur * 9 + col], sum);
                    cur = dd2; sum = 0.0f;
                }
                sum += Vm[ee * 12 + col];
            }
            atomicAdd(&g_vagg[cur * 9 + col], sum);
        }
        __syncthreads();
    }
}

// ---------------- node kernel ----------------
#define N_W1 0
#define N_B1 (256 * 64)
#define N_W2 (N_B1 + 64)
#define N_B2 (N_W2 + 64 * 128)
#define N_XT (N_B2 + 128)
#define N_UT (N_XT + 256 * 68)
#define N_TOT (N_UT + 64 * 68)          // 46528 floats = 186112 B

__global__ void __launch_bounds__(256, 1) k_node(
    const float* __restrict__ Wn1, const float* __restrict__ bn1,
    const float* __restrict__ Wn2, const float* __restrict__ bn2)
{
    extern __shared__ float sm[];
    float* W1s = sm + N_W1;
    float* b1s = sm + N_B1;
    float* W2s = sm + N_W2;
    float* b2s = sm + N_B2;
    float* Xt  = sm + N_XT;
    float* Ut  = sm + N_UT;

    const int tid = threadIdx.x;
    for (int i = tid; i < 256 * 64; i += 256) W1s[i] = Wn1[i];
    for (int i = tid; i < 64 * 128; i += 256) W2s[i] = Wn2[i];
    if (tid < 64) b1s[tid] = bn1[tid];
    if (tid < 128) b2s[tid] = bn2[tid];
    __syncthreads();

    const int wid = tid >> 5, lane = tid & 31;

    for (int tile = blockIdx.x; tile < NT_N; tile += gridDim.x) {
        const int base = tile * TN;
        const int nNd = min(TN, NN - base);

        for (int ii = wid; ii < TN; ii += 8) {
            const int n = base + ii;
            const bool valid = (ii < nNd);
            const float* sp = &g_sbuf[(valid ? n : 0) * SD];
            const float* ap = &g_sagg[(valid ? n : 0) * SD];
            #pragma unroll
            for (int k4 = 0; k4 < 4; k4++) {
                int k = lane + k4 * 32;
                Xt[k * 68 + ii]        = valid ? sp[k] : 0.0f;
                Xt[(SD + k) * 68 + ii] = valid ? ap[k] : 0.0f;
            }
        }
        __syncthreads();

        {
            const int ox = (tid & 15) * 4;
            const int ey = (tid >> 4) * 4;
            float acc[4][4];
            #pragma unroll
            for (int j = 0; j < 4; j++) {
                float b = b1s[ox + j];
                acc[0][j] = b; acc[1][j] = b; acc[2][j] = b; acc[3][j] = b;
            }
            #pragma unroll 4
            for (int k = 0; k < 256; k++) {
                float4 w = *(const float4*)(W1s + k * 64 + ox);
                float4 x = *(const float4*)(Xt + k * 68 + ey);
                acc[0][0] += x.x * w.x; acc[0][1] += x.x * w.y; acc[0][2] += x.x * w.z; acc[0][3] += x.x * w.w;
                acc[1][0] += x.y * w.x; acc[1][1] += x.y * w.y; acc[1][2] += x.y * w.z; acc[1][3] += x.y * w.w;
                acc[2][0] += x.z * w.x; acc[2][1] += x.z * w.y; acc[2][2] += x.z * w.z; acc[2][3] += x.z * w.w;
                acc[3][0] += x.w * w.x; acc[3][1] += x.w * w.y; acc[3][2] += x.w * w.z; acc[3][3] += x.w * w.w;
            }
            #pragma unroll
            for (int j = 0; j < 4; j++)
                #pragma unroll
                for (int i = 0; i < 4; i++)
                    Ut[(ox + j) * 68 + ey + i] = silu_f(acc[i][j]);
        }
        __syncthreads();

        {
            const int ox = (tid & 15) * 8;
            const int ey = (tid >> 4) * 4;
            float acc[4][8];
            #pragma unroll
            for (int j = 0; j < 8; j++) {
                float b = b2s[ox + j];
                acc[0][j] = b; acc[1][j] = b; acc[2][j] = b; acc[3][j] = b;
            }
            #pragma unroll 4
            for (int k = 0; k < 64; k++) {
                float4 wa = *(const float4*)(W2s + k * 128 + ox);
                float4 wb = *(const float4*)(W2s + k * 128 + ox + 4);
                float4 x = *(const float4*)(Ut + k * 68 + ey);
                acc[0][0] += x.x * wa.x; acc[0][1] += x.x * wa.y; acc[0][2] += x.x * wa.z; acc[0][3] += x.x * wa.w;
                acc[0][4] += x.x * wb.x; acc[0][5] += x.x * wb.y; acc[0][6] += x.x * wb.z; acc[0][7] += x.x * wb.w;
                acc[1][0] += x.y * wa.x; acc[1][1] += x.y * wa.y; acc[1][2] += x.y * wa.z; acc[1][3] += x.y * wa.w;
                acc[1][4] += x.y * wb.x; acc[1][5] += x.y * wb.y; acc[1][6] += x.y * wb.z; acc[1][7] += x.y * wb.w;
                acc[2][0] += x.z * wa.x; acc[2][1] += x.z * wa.y; acc[2][2] += x.z * wa.z; acc[2][3] += x.z * wa.w;
                acc[2][4] += x.z * wb.x; acc[2][5] += x.z * wb.y; acc[2][6] += x.z * wb.z; acc[2][7] += x.z * wb.w;
                acc[3][0] += x.w * wa.x; acc[3][1] += x.w * wa.y; acc[3][2] += x.w * wa.z; acc[3][3] += x.w * wa.w;
                acc[3][4] += x.w * wb.x; acc[3][5] += x.w * wb.y; acc[3][6] += x.w * wb.z; acc[3][7] += x.w * wb.w;
            }
            #pragma unroll
            for (int i = 0; i < 4; i++) {
                const int n = base + ey + i;
                if (ey + i < nNd) {
                    float* sp = &g_sbuf[n * SD + ox];
                    #pragma unroll
                    for (int j = 0; j < 8; j++) sp[j] += acc[i][j];
                }
            }
        }
        __syncthreads();
    }
}

// ---------------- host launch ----------------
extern "C" void kernel_launch(void* const* d_in, const int* in_sizes, int n_in,
                              void* d_out, int out_size) {
    const float* s   = (const float*)d_in[0];
    const float* v   = (const float*)d_in[1];
    const int*   ei  = (const int*)d_in[2];
    const float* d   = (const float*)d_in[3];
    const float* r   = (const float*)d_in[4];
    const float* W1  = (const float*)d_in[5];
    const float* b1  = (const float*)d_in[6];
    const float* W2  = (const float*)d_in[7];
    const float* b2  = (const float*)d_in[8];
    const float* W3  = (const float*)d_in[9];
    const float* b3  = (const float*)d_in[10];
    const float* Wn1 = (const float*)d_in[11];
    const float* bn1 = (const float*)d_in[12];
    const float* Wn2 = (const float*)d_in[13];
    const float* bn2 = (const float*)d_in[14];
    float* out = (float*)d_out;

    const int psm = P_TOT * 4;
    const int esm = E_TOT * 4;
    const int nsm = N_TOT * 4;
    cudaFuncSetAttribute(k_proj, cudaFuncAttributeMaxDynamicSharedMemorySize, psm);
    cudaFuncSetAttribute(k_edge, cudaFuncAttributeMaxDynamicSharedMemorySize, esm);
    cudaFuncSetAttribute(k_node, cudaFuncAttributeMaxDynamicSharedMemorySize, nsm);

    k_init<<<1024, 256>>>(s, v);
    k_cnt<<<(EE + 255) / 256, 256>>>(ei);
    k_scan<<<1, 1024>>>();
    k_perm<<<(EE + 255) / 256, 256>>>(ei, d, r);

    for (int l = 0; l < DEPTH; l++) {
        k_zero<<<1024, 256>>>();
        k_proj<<<NT_N, 256, psm>>>(W1 + l * 257 * 64);
        k_edge<<<304, 256, esm>>>(W1 + l * 257 * 64, b1 + l * 64,
                                  W2 + l * 64 * 64, b2 + l * 64,
                                  W3 + l * 64 * 134, b3 + l * 134);
        k_node<<<152, 256, nsm>>>(Wn1 + l * 256 * 64, bn1 + l * 64,
                                  Wn2 + l * 64 * 128, bn2 + l * 128);
        k_vupd<<<(NN * 9 + 255) / 256, 256>>>();
    }
    k_out<<<1024, 256>>>(out);
}

// round 5
// speedup vs baseline: 2.3233x; 1.0873x over previous
#include <cuda_runtime.h>

#define NN 50000
#define EE 500000
#define SD 128
#define HID 64
#define DEPTH 4
#define CUTF 5.0f
#define PI_F 3.14159265358979f

#define TE 64
#define NT_E ((EE + TE - 1) / TE)
#define TN 64
#define NT_N ((NN + TN - 1) / TN)

// ---------------- device scratch ----------------
__device__ float g_sbuf[NN * SD];
__device__ float g_vbuf[NN * 9];
__device__ float g_sagg[NN * SD];
__device__ float g_vagg[NN * 9];
__device__ float g_Pa[NN * HID];
__device__ float g_Pb[NN * HID];
__device__ float g_icnt[NN];
__device__ int   g_cnti[NN];
__device__ int   g_cur[NN];
__device__ int   g_dstS[EE];
__device__ int   g_srcS[EE];
__device__ float g_Cs[EE];
__device__ float g_dsrt[EE];
__device__ float g_rs[EE * 3];

__device__ __forceinline__ float silu_f(float x) {
    return x / (1.0f + __expf(-x));
}

// packed f32x2 FMA: acc.lo += a.lo*b.lo ; acc.hi += a.hi*b.hi
__device__ __forceinline__ void ffma2(unsigned long long& acc,
                                      unsigned long long a, unsigned long long b) {
    asm("fma.rn.f32x2 %0, %1, %2, %0;" : "+l"(acc) : "l"(a), "l"(b));
}
__device__ __forceinline__ unsigned long long packlo(float x) {
    return (unsigned long long)__float_as_uint(x);
}
__device__ __forceinline__ float f2x_sum(unsigned long long a) {
    float lo = __int_as_float((unsigned)(a & 0xffffffffull));
    float hi = __int_as_float((unsigned)(a >> 32));
    return lo + hi;
}

// ---------------- small kernels ----------------
__global__ void k_init(const float* __restrict__ s, const float* __restrict__ v) {
    int i = blockIdx.x * blockDim.x + threadIdx.x;
    int stride = gridDim.x * blockDim.x;
    for (int j = i; j < NN * SD; j += stride) g_sbuf[j] = s[j];
    for (int j = i; j < NN * 9; j += stride) g_vbuf[j] = v[j];
    for (int j = i; j < NN; j += stride) g_cnti[j] = 0;
}

__global__ void k_cnt(const int* __restrict__ ei) {
    int e = blockIdx.x * blockDim.x + threadIdx.x;
    if (e < EE) atomicAdd(&g_cnti[ei[e]], 1);
}

__global__ void k_scan() {
    __shared__ int sh[1024];
    __shared__ int carry;
    int tid = threadIdx.x;
    if (tid == 0) carry = 0;
    __syncthreads();
    for (int base = 0; base < NN; base += 1024) {
        int i = base + tid;
        int x = (i < NN) ? g_cnti[i] : 0;
        sh[tid] = x;
        __syncthreads();
        for (int off = 1; off < 1024; off <<= 1) {
            int t = (tid >= off) ? sh[tid - off] : 0;
            __syncthreads();
            sh[tid] += t;
            __syncthreads();
        }
        if (i < NN) {
            g_cur[i] = carry + sh[tid] - x;
            g_icnt[i] = 1.0f / fmaxf((float)x, 1.0f);
        }
        __syncthreads();
        if (tid == 1023) carry += sh[1023];
        __syncthreads();
    }
}

__global__ void k_perm(const int* __restrict__ ei, const float* __restrict__ d,
                       const float* __restrict__ r) {
    int e = blockIdx.x * blockDim.x + threadIdx.x;
    if (e < EE) {
        int dst = ei[e];
        int pos = atomicAdd(&g_cur[dst], 1);
        g_dstS[pos] = dst;
        g_srcS[pos] = ei[EE + e];
        float dd = d[e];
        g_dsrt[pos] = dd;
        g_Cs[pos] = (dd < CUTF) ? 0.5f * (cosf(PI_F * dd / CUTF) + 1.0f) : 0.0f;
        g_rs[pos * 3 + 0] = r[e * 3 + 0];
        g_rs[pos * 3 + 1] = r[e * 3 + 1];
        g_rs[pos * 3 + 2] = r[e * 3 + 2];
    }
}

__global__ void k_zero() {
    int i = blockIdx.x * blockDim.x + threadIdx.x;
    int stride = gridDim.x * blockDim.x;
    for (int j = i; j < NN * SD; j += stride) g_sagg[j] = 0.0f;
    for (int j = i; j < NN * 9; j += stride) g_vagg[j] = 0.0f;
}

__global__ void k_vupd() {
    int i = blockIdx.x * blockDim.x + threadIdx.x;
    if (i < NN * 9) {
        int n = i / 9;
        g_vbuf[i] += g_vagg[i] * g_icnt[n];
        g_vagg[i] = 0.0f;   // pre-zero for next layer
    }
}

__global__ void k_out(float* __restrict__ out) {
    int i = blockIdx.x * blockDim.x + threadIdx.x;
    int stride = gridDim.x * blockDim.x;
    for (int j = i; j < NN * SD; j += stride) out[j] = g_sbuf[j];
    for (int j = i; j < NN * 9; j += stride) out[NN * SD + j] = g_vbuf[j];
}

// ---------------- projection: Pa = S @ W1[0:128], Pb = S @ W1[128:256] ----------------
// k-major layouts: Ws [128 o][132 k], Xt [64 n][132 k]
#define P_W 0
#define P_X (P_W + 128 * 132)           // 16896
#define P_TOT (P_X + 64 * 132)          // 25344 floats = 101376 B

__global__ void __launch_bounds__(256, 2) k_proj(const float* __restrict__ W1) {
    extern __shared__ float sm[];
    float* Ws = sm + P_W;
    float* Xt = sm + P_X;

    const int tid = threadIdx.x;
    // transpose-load W1: Ws[o][k] ; o<64 -> W1[k][o], o>=64 -> W1[128+k][o-64]
    for (int i = tid; i < 128 * 128; i += 256) {
        int k = i >> 7, o = i & 127;
        float w = (o < 64) ? W1[k * 64 + o] : W1[(128 + k) * 64 + (o - 64)];
        Ws[o * 132 + k] = w;
    }

    const int wid = tid >> 5, lane = tid & 31;
    const int base = blockIdx.x * TN;
    const int nNd = min(TN, NN - base);

    for (int ii = wid; ii < TN; ii += 8) {
        const int n = base + ii;
        const bool valid = (ii < nNd);
        const float4* sp = (const float4*)&g_sbuf[(valid ? n : 0) * SD];
        float4 x = sp[lane];
        if (!valid) x = make_float4(0.f, 0.f, 0.f, 0.f);
        *(float4*)(Xt + ii * 132 + lane * 4) = x;
    }
    __syncthreads();

    const int oc = tid & 31;            // o in {oc, oc+32, oc+64, oc+96}
    const int eg = tid >> 5;            // n = eg*8 .. +7
    unsigned long long acc[8][4];
    #pragma unroll
    for (int i = 0; i < 8; i++)
        #pragma unroll
        for (int j = 0; j < 4; j++) acc[i][j] = 0ull;

    #pragma unroll 2
    for (int k = 0; k < 128; k += 4) {
        ulonglong2 w[4];
        #pragma unroll
        for (int j = 0; j < 4; j++)
            w[j] = *(const ulonglong2*)(Ws + (oc + 32 * j) * 132 + k);
        #pragma unroll
        for (int i = 0; i < 8; i++) {
            ulonglong2 x = *(const ulonglong2*)(Xt + (eg * 8 + i) * 132 + k);
            #pragma unroll
            for (int j = 0; j < 4; j++) {
                ffma2(acc[i][j], x.x, w[j].x);
                ffma2(acc[i][j], x.y, w[j].y);
            }
        }
    }

    #pragma unroll
    for (int i = 0; i < 8; i++) {
        const int n = base + eg * 8 + i;
        if (eg * 8 + i < nNd) {
            #pragma unroll
            for (int j = 0; j < 4; j++) {
                const int o = oc + 32 * j;
                float val = f2x_sum(acc[i][j]);
                if (o < 64) g_Pa[n * HID + o] = val;
                else        g_Pb[n * HID + (o - 64)] = val;
            }
        }
    }
}

// ---------------- edge kernel (dst-sorted, f32x2) ----------------
#define E_W2T 0
#define E_W3T (E_W2T + 64 * 68)         // 4352
#define E_B1  (E_W3T + 134 * 68)        // 13464
#define E_B2  (E_B1 + 64)
#define E_B3  (E_B2 + 64)
#define E_W1D (E_B3 + 136)
#define E_H1  (E_W1D + 64)              // 13728
#define E_H2  (E_H1 + 64 * 68)          // 18080
#define E_VM  (E_H2 + 64 * 68)          // 22432
#define E_CS  (E_VM + 64 * 12)          // 23200
#define E_DS  (E_CS + 64)
#define E_SS  (E_DS + 64)
#define E_TOT (E_SS + 64)               // 23392 floats = 93568 B

__global__ void __launch_bounds__(256, 2) k_edge(
    const float* __restrict__ W1, const float* __restrict__ b1,
    const float* __restrict__ W2, const float* __restrict__ b2,
    const float* __restrict__ W3, const float* __restrict__ b3)
{
    extern __shared__ float sm[];
    float* W2t = sm + E_W2T;   // [64 o][68 k]
    float* W3t = sm + E_W3T;   // [134 o][68 k]
    float* b1s = sm + E_B1;
    float* b2s = sm + E_B2;
    float* b3s = sm + E_B3;
    float* w1d = sm + E_W1D;
    float* H1e = sm + E_H1;    // [64 e][68 k]
    float* H2e = sm + E_H2;    // [64 e][68 k]
    float* Vm  = sm + E_VM;    // [64 e][12]
    float* CS  = sm + E_CS;
    int*   dstSh = (int*)(sm + E_DS);
    int*   srcSh = (int*)(sm + E_SS);

    const int tid = threadIdx.x;

    // transpose-stage weights
    for (int i = tid; i < 64 * 64; i += 256) {
        int k = i >> 6, o = i & 63;
        W2t[o * 68 + k] = W2[k * 64 + o];
    }
    for (int i = tid; i < 64 * 134; i += 256) {
        int k = i / 134, o = i % 134;
        W3t[o * 68 + k] = W3[k * 134 + o];
    }
    if (tid < 64) {
        b1s[tid] = b1[tid];
        b2s[tid] = b2[tid];
        w1d[tid] = W1[256 * 64 + tid];
    }
    for (int i = tid; i < 134; i += 256) b3s[i] = b3[i];
    __syncthreads();

    const int wid = tid >> 5, lane = tid & 31;

    for (int tile = blockIdx.x; tile < NT_E; tile += gridDim.x) {
        const int base = tile * TE;
        const int nE = min(TE, EE - base);

        // ---- gather + silu -> H1e [e][k] ----
        for (int ee = wid; ee < TE; ee += 8) {
            const int epos = base + ee;
            const bool valid = (ee < nE);
            int dst = 0, src = 0;
            float dd = 0.0f;
            if (valid) { dst = g_dstS[epos]; src = g_srcS[epos]; dd = g_dsrt[epos]; }
            const float2 a = ((const float2*)&g_Pa[dst * HID])[lane];
            const float2 b = ((const float2*)&g_Pb[src * HID])[lane];
            const int k0 = lane * 2;
            float h0 = a.x + b.x + dd * w1d[k0] + b1s[k0];
            float h1 = a.y + b.y + dd * w1d[k0 + 1] + b1s[k0 + 1];
            float2 hv;
            hv.x = valid ? silu_f(h0) : 0.0f;
            hv.y = valid ? silu_f(h1) : 0.0f;
            *(float2*)(H1e + ee * 68 + k0) = hv;
            if (lane == 0) {
                CS[ee] = valid ? g_Cs[epos] : 0.0f;
                dstSh[ee] = dst; srcSh[ee] = src;
            }
        }
        __syncthreads();

        // ---- GEMM2: H2e[e][o] = silu(H1e @ W2 + b2) ----
        {
            const int oc = tid & 15;   // o in {oc, oc+16, oc+32, oc+48}
            const int eg = tid >> 4;   // e = eg*4..+3
            unsigned long long acc[4][4];
            #pragma unroll
            for (int i = 0; i < 4; i++)
                #pragma unroll
                for (int j = 0; j < 4; j++) acc[i][j] = packlo(b2s[oc + 16 * j]);
            #pragma unroll 4
            for (int k = 0; k < 64; k += 4) {
                ulonglong2 w[4];
                #pragma unroll
                for (int j = 0; j < 4; j++)
                    w[j] = *(const ulonglong2*)(W2t + (oc + 16 * j) * 68 + k);
                #pragma unroll
                for (int i = 0; i < 4; i++) {
                    ulonglong2 x = *(const ulonglong2*)(H1e + (eg * 4 + i) * 68 + k);
                    #pragma unroll
                    for (int j = 0; j < 4; j++) {
                        ffma2(acc[i][j], x.x, w[j].x);
                        ffma2(acc[i][j], x.y, w[j].y);
                    }
                }
            }
            #pragma unroll
            for (int i = 0; i < 4; i++)
                #pragma unroll
                for (int j = 0; j < 4; j++)
                    H2e[(eg * 4 + i) * 68 + oc + 16 * j] = silu_f(f2x_sum(acc[i][j]));
        }
        __syncthreads();

        // ---- GEMM3 scalar: [64e x 64] @ [64 x 128], run-reduced scatter ----
        {
            const int oc = tid & 31;   // o in {oc, oc+32, oc+64, oc+96}
            const int eg = tid >> 5;   // e = eg*8..+7
            unsigned long long acc[8][4];
            #pragma unroll
            for (int i = 0; i < 8; i++)
                #pragma unroll
                for (int j = 0; j < 4; j++) acc[i][j] = packlo(b3s[oc + 32 * j]);
            #pragma unroll 4
            for (int k = 0; k < 64; k += 4) {
                ulonglong2 w[4];
                #pragma unroll
                for (int j = 0; j < 4; j++)
                    w[j] = *(const ulonglong2*)(W3t + (oc + 32 * j) * 68 + k);
                #pragma unroll
                for (int i = 0; i < 8; i++) {
                    ulonglong2 x = *(const ulonglong2*)(H2e + (eg * 8 + i) * 68 + k);
                    #pragma unroll
                    for (int j = 0; j < 4; j++) {
                        ffma2(acc[i][j], x.x, w[j].x);
                        ffma2(acc[i][j], x.y, w[j].y);
                    }
                }
            }
            // run-detected flush over 8 consecutive sorted edges
            int cur = dstSh[eg * 8];
            float s4[4] = {0.f, 0.f, 0.f, 0.f};
            #pragma unroll
            for (int i = 0; i < 8; i++) {
                const int ee = eg * 8 + i;
                int dd2 = dstSh[ee];
                if (dd2 != cur) {
                    #pragma unroll
                    for (int j = 0; j < 4; j++)
                        atomicAdd(&g_sagg[cur * SD + oc + 32 * j], s4[j]);
                    cur = dd2;
                    s4[0] = s4[1] = s4[2] = s4[3] = 0.f;
                }
                float c = CS[ee];
                #pragma unroll
                for (int j = 0; j < 4; j++) s4[j] += f2x_sum(acc[i][j]) * c;
            }
            #pragma unroll
            for (int j = 0; j < 4; j++)
                atomicAdd(&g_sagg[cur * SD + oc + 32 * j], s4[j]);
        }

        // ---- vector gates -> Vm ----
        if (tid < TE) {
            const int ee = tid;
            const int epos = base + ee;
            float a6[6];
            #pragma unroll
            for (int j = 0; j < 6; j++) a6[j] = b3s[128 + j];
            #pragma unroll 8
            for (int k = 0; k < 64; k++) {
                float x = H2e[ee * 68 + k];
                #pragma unroll
                for (int j = 0; j < 6; j++) a6[j] += x * W3t[(128 + j) * 68 + k];
            }
            const float c = CS[ee];
            const int src = srcSh[ee];
            float rv[3];
            #pragma unroll
            for (int x = 0; x < 3; x++) rv[x] = (epos < EE) ? g_rs[epos * 3 + x] : 0.0f;
            #pragma unroll
            for (int vi = 0; vi < 3; vi++) {
                const float gv = a6[vi], gr = a6[3 + vi];
                #pragma unroll
                for (int x = 0; x < 3; x++)
                    Vm[ee * 12 + vi * 3 + x] =
                        (g_vbuf[src * 9 + vi * 3 + x] * gv + rv[x] * gr) * c;
            }
        }
        __syncthreads();

        // ---- group-reduce Vm -> v_agg ----
        if (tid < 36) {
            const int col = tid % 9, seg = tid / 9;
            const int e0 = seg * 16;
            int cur = dstSh[e0];
            float sum = 0.0f;
            #pragma unroll 4
            for (int i = 0; i < 16; i++) {
                int ee = e0 + i;
                int dd2 = dstSh[ee];
                if (dd2 != cur) {
                    atomicAdd(&g_vagg[cur * 9 + col], sum);
                    cur = dd2; sum = 0.0f;
                }
                sum += Vm[ee * 12 + col];
            }
            atomicAdd(&g_vagg[cur * 9 + col], sum);
        }
        __syncthreads();
    }
}

// ---------------- node kernel (f32x2) ----------------
#define N_W1T 0
#define N_W2T (N_W1T + 64 * 260)        // 16640
#define N_B1  (N_W2T + 128 * 68)        // 25344
#define N_B2  (N_B1 + 64)
#define N_XT  (N_B2 + 128)              // 25536
#define N_UT  (N_XT + 64 * 260)         // 42176
#define N_TOT (N_UT + 64 * 68)          // 46528 floats = 186112 B

__global__ void __launch_bounds__(256, 1) k_node(
    const float* __restrict__ Wn1, const float* __restrict__ bn1,
    const float* __restrict__ Wn2, const float* __restrict__ bn2)
{
    extern __shared__ float sm[];
    float* W1t = sm + N_W1T;   // [64 o][260 k]
    float* W2t = sm + N_W2T;   // [128 o][68 k]
    float* b1s = sm + N_B1;
    float* b2s = sm + N_B2;
    float* Xt  = sm + N_XT;    // [64 n][260 k]
    float* Ut  = sm + N_UT;    // [64 n][68 k]

    const int tid = threadIdx.x;
    for (int i = tid; i < 64 * 256; i += 256) {
        int k = i >> 6, o = i & 63;
        W1t[o * 260 + k] = Wn1[k * 64 + o];
    }
    for (int i = tid; i < 128 * 64; i += 256) {
        int k = i >> 7, o = i & 127;
        W2t[o * 68 + k] = Wn2[k * 128 + o];
    }
    if (tid < 64) b1s[tid] = bn1[tid];
    if (tid < 128) b2s[tid] = bn2[tid];
    __syncthreads();

    const int wid = tid >> 5, lane = tid & 31;

    for (int tile = blockIdx.x; tile < NT_N; tile += gridDim.x) {
        const int base = tile * TN;
        const int nNd = min(TN, NN - base);

        for (int ii = wid; ii < TN; ii += 8) {
            const int n = base + ii;
            const bool valid = (ii < nNd);
            const float4* sp = (const float4*)&g_sbuf[(valid ? n : 0) * SD];
            float4* ap = (float4*)&g_sagg[(valid ? n : 0) * SD];
            float4 xs = sp[lane];
            float4 xa = ap[lane];
            if (!valid) { xs = make_float4(0,0,0,0); xa = xs; }
            *(float4*)(Xt + ii * 260 + lane * 4) = xs;
            *(float4*)(Xt + ii * 260 + 128 + lane * 4) = xa;
            if (valid) ap[lane] = make_float4(0, 0, 0, 0);   // pre-zero for next layer
        }
        __syncthreads();

        // GEMM1: Ut = silu([s, s_agg] @ Wn1 + bn1)
        {
            const int oc = tid & 15;
            const int eg = tid >> 4;
            unsigned long long acc[4][4];
            #pragma unroll
            for (int i = 0; i < 4; i++)
                #pragma unroll
                for (int j = 0; j < 4; j++) acc[i][j] = packlo(b1s[oc + 16 * j]);
            #pragma unroll 2
            for (int k = 0; k < 256; k += 4) {
                ulonglong2 w[4];
                #pragma unroll
                for (int j = 0; j < 4; j++)
                    w[j] = *(const ulonglong2*)(W1t + (oc + 16 * j) * 260 + k);
                #pragma unroll
                for (int i = 0; i < 4; i++) {
                    ulonglong2 x = *(const ulonglong2*)(Xt + (eg * 4 + i) * 260 + k);
                    #pragma unroll
                    for (int j = 0; j < 4; j++) {
                        ffma2(acc[i][j], x.x, w[j].x);
                        ffma2(acc[i][j], x.y, w[j].y);
                    }
                }
            }
            #pragma unroll
            for (int i = 0; i < 4; i++)
                #pragma unroll
                for (int j = 0; j < 4; j++)
                    Ut[(eg * 4 + i) * 68 + oc + 16 * j] = silu_f(f2x_sum(acc[i][j]));
        }
        __syncthreads();

        // GEMM2: s += Ut @ Wn2 + bn2
        {
            const int oc = tid & 31;
            const int eg = tid >> 5;
            unsigned long long acc[8][4];
            #pragma unroll
            for (int i = 0; i < 8; i++)
                #pragma unroll
                for (int j = 0; j < 4; j++) acc[i][j] = packlo(b2s[oc + 32 * j]);
            #pragma unroll 4
            for (int k = 0; k < 64; k += 4) {
                ulonglong2 w[4];
                #pragma unroll
                for (int j = 0; j < 4; j++)
                    w[j] = *(const ulonglong2*)(W2t + (oc + 32 * j) * 68 + k);
                #pragma unroll
                for (int i = 0; i < 8; i++) {
                    ulonglong2 x = *(const ulonglong2*)(Ut + (eg * 8 + i) * 68 + k);
                    #pragma unroll
                    for (int j = 0; j < 4; j++) {
                        ffma2(acc[i][j], x.x, w[j].x);
                        ffma2(acc[i][j], x.y, w[j].y);
                    }
                }
            }
            #pragma unroll
            for (int i = 0; i < 8; i++) {
                const int n = base + eg * 8 + i;
                if (eg * 8 + i < nNd) {
                    #pragma unroll
                    for (int j = 0; j < 4; j++)
                        g_sbuf[n * SD + oc + 32 * j] += f2x_sum(acc[i][j]);
                }
            }
        }
        __syncthreads();
    }
}

// ---------------- host launch ----------------
extern "C" void kernel_launch(void* const* d_in, const int* in_sizes, int n_in,
                              void* d_out, int out_size) {
    const float* s   = (const float*)d_in[0];
    const float* v   = (const float*)d_in[1];
    const int*   ei  = (const int*)d_in[2];
    const float* d   = (const float*)d_in[3];
    const float* r   = (const float*)d_in[4];
    const float* W1  = (const float*)d_in[5];
    const float* b1  = (const float*)d_in[6];
    const float* W2  = (const float*)d_in[7];
    const float* b2  = (const float*)d_in[8];
    const float* W3  = (const float*)d_in[9];
    const float* b3  = (const float*)d_in[10];
    const float* Wn1 = (const float*)d_in[11];
    const float* bn1 = (const float*)d_in[12];
    const float* Wn2 = (const float*)d_in[13];
    const float* bn2 = (const float*)d_in[14];
    float* out = (float*)d_out;

    const int psm = P_TOT * 4;
    const int esm = E_TOT * 4;
    const int nsm = N_TOT * 4;
    cudaFuncSetAttribute(k_proj, cudaFuncAttributeMaxDynamicSharedMemorySize, psm);
    cudaFuncSetAttribute(k_edge, cudaFuncAttributeMaxDynamicSharedMemorySize, esm);
    cudaFuncSetAttribute(k_node, cudaFuncAttributeMaxDynamicSharedMemorySize, nsm);

    k_init<<<1024, 256>>>(s, v);
    k_cnt<<<(EE + 255) / 256, 256>>>(ei);
    k_scan<<<1, 1024>>>();
    k_perm<<<(EE + 255) / 256, 256>>>(ei, d, r);
    k_zero<<<1024, 256>>>();   // once; subsequent zeroing fused into k_node/k_vupd

    for (int l = 0; l < DEPTH; l++) {
        k_proj<<<NT_N, 256, psm>>>(W1 + l * 257 * 64);
        k_edge<<<304, 256, esm>>>(W1 + l * 257 * 64, b1 + l * 64,
                                  W2 + l * 64 * 64, b2 + l * 64,
                                  W3 + l * 64 * 134, b3 + l * 134);
        k_node<<<152, 256, nsm>>>(Wn1 + l * 256 * 64, bn1 + l * 64,
                                  Wn2 + l * 64 * 128, bn2 + l * 128);
        k_vupd<<<(NN * 9 + 255) / 256, 256>>>();
    }
    k_out<<<1024, 256>>>(out);
}

// round 6
// speedup vs baseline: 2.4340x; 1.0477x over previous
#include <cuda_runtime.h>

#define NN 50000
#define EE 500000
#define SD 128
#define HID 64
#define DEPTH 4
#define CUTF 5.0f
#define PI_F 3.14159265358979f

#define TE 64
#define NT_E ((EE + TE - 1) / TE)
#define TN 64
#define NT_N ((NN + TN - 1) / TN)

// ---------------- device scratch ----------------
__device__ float g_sbuf[NN * SD];
__device__ float g_vbuf[NN * 9];
__device__ float g_sagg[NN * SD];
__device__ float g_vagg[NN * 9];
__device__ float g_Pa[NN * HID];
__device__ float g_Pb[NN * HID];
__device__ float g_icnt[NN];
__device__ int   g_cnti[NN];
__device__ int   g_cur[NN];
__device__ int   g_dstS[EE];
__device__ int   g_srcS[EE];
__device__ float g_Cs[EE];
__device__ float g_dsrt[EE];
__device__ float g_rs[EE * 3];

__device__ __forceinline__ float silu_f(float x) {
    return x / (1.0f + __expf(-x));
}

__device__ __forceinline__ void ffma2(unsigned long long& acc,
                                      unsigned long long a, unsigned long long b) {
    asm("fma.rn.f32x2 %0, %1, %2, %0;" : "+l"(acc) : "l"(a), "l"(b));
}
__device__ __forceinline__ unsigned long long packlo(float x) {
    return (unsigned long long)__float_as_uint(x);
}
__device__ __forceinline__ float f2x_sum(unsigned long long a) {
    float lo = __int_as_float((unsigned)(a & 0xffffffffull));
    float hi = __int_as_float((unsigned)(a >> 32));
    return lo + hi;
}

// ---------------- small kernels ----------------
__global__ void k_init(const float* __restrict__ s, const float* __restrict__ v) {
    int i = blockIdx.x * blockDim.x + threadIdx.x;
    int stride = gridDim.x * blockDim.x;
    for (int j = i; j < NN * SD; j += stride) g_sbuf[j] = s[j];
    for (int j = i; j < NN * 9; j += stride) g_vbuf[j] = v[j];
    for (int j = i; j < NN; j += stride) g_cnti[j] = 0;
}

__global__ void k_cnt(const int* __restrict__ ei) {
    int e = blockIdx.x * blockDim.x + threadIdx.x;
    if (e < EE) atomicAdd(&g_cnti[ei[e]], 1);
}

__global__ void k_scan() {
    __shared__ int sh[1024];
    __shared__ int carry;
    int tid = threadIdx.x;
    if (tid == 0) carry = 0;
    __syncthreads();
    for (int base = 0; base < NN; base += 1024) {
        int i = base + tid;
        int x = (i < NN) ? g_cnti[i] : 0;
        sh[tid] = x;
        __syncthreads();
        for (int off = 1; off < 1024; off <<= 1) {
            int t = (tid >= off) ? sh[tid - off] : 0;
            __syncthreads();
            sh[tid] += t;
            __syncthreads();
        }
        if (i < NN) {
            g_cur[i] = carry + sh[tid] - x;
            g_icnt[i] = 1.0f / fmaxf((float)x, 1.0f);
        }
        __syncthreads();
        if (tid == 1023) carry += sh[1023];
        __syncthreads();
    }
}

__global__ void k_perm(const int* __restrict__ ei, const float* __restrict__ d,
                       const float* __restrict__ r) {
    int e = blockIdx.x * blockDim.x + threadIdx.x;
    if (e < EE) {
        int dst = ei[e];
        int pos = atomicAdd(&g_cur[dst], 1);
        g_dstS[pos] = dst;
        g_srcS[pos] = ei[EE + e];
        float dd = d[e];
        g_dsrt[pos] = dd;
        g_Cs[pos] = (dd < CUTF) ? 0.5f * (cosf(PI_F * dd / CUTF) + 1.0f) : 0.0f;
        g_rs[pos * 3 + 0] = r[e * 3 + 0];
        g_rs[pos * 3 + 1] = r[e * 3 + 1];
        g_rs[pos * 3 + 2] = r[e * 3 + 2];
    }
}

__global__ void k_zero() {
    int i = blockIdx.x * blockDim.x + threadIdx.x;
    int stride = gridDim.x * blockDim.x;
    for (int j = i; j < NN * SD; j += stride) g_sagg[j] = 0.0f;
    for (int j = i; j < NN * 9; j += stride) g_vagg[j] = 0.0f;
}

__global__ void k_out(float* __restrict__ out) {
    int i = blockIdx.x * blockDim.x + threadIdx.x;
    int stride = gridDim.x * blockDim.x;
    for (int j = i; j < NN * SD; j += stride) out[j] = g_sbuf[j];
    for (int j = i; j < NN * 9; j += stride) out[NN * SD + j] = g_vbuf[j];
}

// ---------------- projection ----------------
#define P_W 0
#define P_X (P_W + 128 * 132)
#define P_TOT (P_X + 64 * 132)

__global__ void __launch_bounds__(256, 2) k_proj(const float* __restrict__ W1) {
    extern __shared__ float sm[];
    float* Ws = sm + P_W;
    float* Xt = sm + P_X;

    const int tid = threadIdx.x;
    for (int i = tid; i < 128 * 128; i += 256) {
        int k = i >> 7, o = i & 127;
        float w = (o < 64) ? W1[k * 64 + o] : W1[(128 + k) * 64 + (o - 64)];
        Ws[o * 132 + k] = w;
    }

    const int wid = tid >> 5, lane = tid & 31;
    const int base = blockIdx.x * TN;
    const int nNd = min(TN, NN - base);

    for (int ii = wid; ii < TN; ii += 8) {
        const int n = base + ii;
        const bool valid = (ii < nNd);
        const float4* sp = (const float4*)&g_sbuf[(valid ? n : 0) * SD];
        float4 x = sp[lane];
        if (!valid) x = make_float4(0.f, 0.f, 0.f, 0.f);
        *(float4*)(Xt + ii * 132 + lane * 4) = x;
    }
    __syncthreads();

    const int oc = tid & 31;
    const int eg = tid >> 5;
    unsigned long long acc[8][4];
    #pragma unroll
    for (int i = 0; i < 8; i++)
        #pragma unroll
        for (int j = 0; j < 4; j++) acc[i][j] = 0ull;

    #pragma unroll 2
    for (int k = 0; k < 128; k += 4) {
        ulonglong2 w[4];
        #pragma unroll
        for (int j = 0; j < 4; j++)
            w[j] = *(const ulonglong2*)(Ws + (oc + 32 * j) * 132 + k);
        #pragma unroll
        for (int i = 0; i < 8; i++) {
            ulonglong2 x = *(const ulonglong2*)(Xt + (eg * 8 + i) * 132 + k);
            #pragma unroll
            for (int j = 0; j < 4; j++) {
                ffma2(acc[i][j], x.x, w[j].x);
                ffma2(acc[i][j], x.y, w[j].y);
            }
        }
    }

    #pragma unroll
    for (int i = 0; i < 8; i++) {
        const int n = base + eg * 8 + i;
        if (eg * 8 + i < nNd) {
            #pragma unroll
            for (int j = 0; j < 4; j++) {
                const int o = oc + 32 * j;
                float val = f2x_sum(acc[i][j]);
                if (o < 64) g_Pa[n * HID + o] = val;
                else        g_Pb[n * HID + (o - 64)] = val;
            }
        }
    }
}

// ---------------- edge kernel (dst-sorted, f32x2, cp.async Pb pipeline) ----------------
#define E_W2T 0
#define E_W3T (E_W2T + 64 * 68)         // 4352
#define E_B1  (E_W3T + 134 * 68)        // 13464
#define E_B2  (E_B1 + 64)
#define E_B3  (E_B2 + 64)
#define E_W1D (E_B3 + 136)
#define E_H1  (E_W1D + 64)              // 13728
#define E_H2  (E_H1 + 64 * 68)          // 18080
#define E_VM  (E_H2 + 64 * 68)          // 22432
#define E_CS  (E_VM + 64 * 12)          // 23200
#define E_DS  (E_CS + 64)
#define E_SS  (E_DS + 64)
#define E_PBN (E_SS + 64)               // 23392 (x4 = 93568 B, 16B aligned)
#define E_TOT (E_PBN + 64 * 64)         // 27488 floats = 109952 B

__device__ __forceinline__ void prefetch_pb(float* PbN, int ntile, int tid) {
    if (ntile < NT_E) {
        const int base2 = ntile * TE;
        const int e = tid >> 2;                       // 0..63
        const int epos = min(base2 + e, EE - 1);
        const int se = g_srcS[epos];
        const int f0 = (tid & 3) * 16;                // float offset within row
        const float* gp = &g_Pb[se * HID + f0];
        unsigned saddr = (unsigned)__cvta_generic_to_shared(PbN + e * 64 + f0);
        #pragma unroll
        for (int c = 0; c < 4; c++)
            asm volatile("cp.async.cg.shared.global [%0], [%1], 16;"
                         :: "r"(saddr + c * 16), "l"(gp + c * 4) : "memory");
    }
    asm volatile("cp.async.commit_group;" ::: "memory");
}

__global__ void __launch_bounds__(256, 2) k_edge(
    const float* __restrict__ W1, const float* __restrict__ b1,
    const float* __restrict__ W2, const float* __restrict__ b2,
    const float* __restrict__ W3, const float* __restrict__ b3)
{
    extern __shared__ float sm[];
    float* W2t = sm + E_W2T;
    float* W3t = sm + E_W3T;
    float* b1s = sm + E_B1;
    float* b2s = sm + E_B2;
    float* b3s = sm + E_B3;
    float* w1d = sm + E_W1D;
    float* H1e = sm + E_H1;
    float* H2e = sm + E_H2;
    float* Vm  = sm + E_VM;
    float* CS  = sm + E_CS;
    int*   dstSh = (int*)(sm + E_DS);
    int*   srcSh = (int*)(sm + E_SS);
    float* PbN = sm + E_PBN;

    const int tid = threadIdx.x;

    for (int i = tid; i < 64 * 64; i += 256) {
        int k = i >> 6, o = i & 63;
        W2t[o * 68 + k] = W2[k * 64 + o];
    }
    for (int i = tid; i < 64 * 134; i += 256) {
        int k = i / 134, o = i % 134;
        W3t[o * 68 + k] = W3[k * 134 + o];
    }
    if (tid < 64) {
        b1s[tid] = b1[tid];
        b2s[tid] = b2[tid];
        w1d[tid] = W1[256 * 64 + tid];
    }
    for (int i = tid; i < 134; i += 256) b3s[i] = b3[i];

    const int wid = tid >> 5, lane = tid & 31;

    // prologue: prefetch first tile's Pb
    prefetch_pb(PbN, blockIdx.x, tid);

    for (int tile = blockIdx.x; tile < NT_E; tile += gridDim.x) {
        const int base = tile * TE;
        const int nE = min(TE, EE - base);

        asm volatile("cp.async.wait_group 0;" ::: "memory");
        __syncthreads();   // PbN visible to all; also covers weight staging on iter 0

        // ---- gather Pa (L1-friendly, sorted) + staged Pb -> silu -> H1e [e][k] ----
        #pragma unroll 2
        for (int i = 0; i < 8; i++) {
            const int ee = wid * 8 + i;
            const int epos = base + ee;
            const bool valid = (ee < nE);
            int dst = 0, src = 0;
            float dd = 0.0f;
            if (valid) { dst = g_dstS[epos]; src = g_srcS[epos]; dd = g_dsrt[epos]; }
            const float2 a = ((const float2*)&g_Pa[dst * HID])[lane];
            const float2 b = ((const float2*)(PbN + ee * 64))[lane];
            const int k0 = lane * 2;
            float h0 = a.x + b.x + dd * w1d[k0] + b1s[k0];
            float h1 = a.y + b.y + dd * w1d[k0 + 1] + b1s[k0 + 1];
            float2 hv;
            hv.x = valid ? silu_f(h0) : 0.0f;
            hv.y = valid ? silu_f(h1) : 0.0f;
            *(float2*)(H1e + ee * 68 + k0) = hv;
            if (lane == 0) {
                CS[ee] = valid ? g_Cs[epos] : 0.0f;
                dstSh[ee] = dst; srcSh[ee] = src;
            }
        }
        __syncthreads();   // H1e ready; PbN reads complete

        // issue next tile's Pb prefetch — overlaps GEMM2/GEMM3/vector phases
        prefetch_pb(PbN, tile + gridDim.x, tid);

        // ---- GEMM2: H2e = silu(H1e @ W2 + b2) ----
        {
            const int oc = tid & 15;
            const int eg = tid >> 4;
            unsigned long long acc[4][4];
            #pragma unroll
            for (int i = 0; i < 4; i++)
                #pragma unroll
                for (int j = 0; j < 4; j++) acc[i][j] = packlo(b2s[oc + 16 * j]);
            #pragma unroll 4
            for (int k = 0; k < 64; k += 4) {
                ulonglong2 w[4];
                #pragma unroll
                for (int j = 0; j < 4; j++)
                    w[j] = *(const ulonglong2*)(W2t + (oc + 16 * j) * 68 + k);
                #pragma unroll
                for (int i = 0; i < 4; i++) {
                    ulonglong2 x = *(const ulonglong2*)(H1e + (eg * 4 + i) * 68 + k);
                    #pragma unroll
                    for (int j = 0; j < 4; j++) {
                        ffma2(acc[i][j], x.x, w[j].x);
                        ffma2(acc[i][j], x.y, w[j].y);
                    }
                }
            }
            #pragma unroll
            for (int i = 0; i < 4; i++)
                #pragma unroll
                for (int j = 0; j < 4; j++)
                    H2e[(eg * 4 + i) * 68 + oc + 16 * j] = silu_f(f2x_sum(acc[i][j]));
        }
        __syncthreads();

        // ---- GEMM3 scalar: run-reduced scatter ----
        {
            const int oc = tid & 31;
            const int eg = tid >> 5;
            unsigned long long acc[8][4];
            #pragma unroll
            for (int i = 0; i < 8; i++)
                #pragma unroll
                for (int j = 0; j < 4; j++) acc[i][j] = packlo(b3s[oc + 32 * j]);
            #pragma unroll 4
            for (int k = 0; k < 64; k += 4) {
                ulonglong2 w[4];
                #pragma unroll
                for (int j = 0; j < 4; j++)
                    w[j] = *(const ulonglong2*)(W3t + (oc + 32 * j) * 68 + k);
                #pragma unroll
                for (int i = 0; i < 8; i++) {
                    ulonglong2 x = *(const ulonglong2*)(H2e + (eg * 8 + i) * 68 + k);
                    #pragma unroll
                    for (int j = 0; j < 4; j++) {
                        ffma2(acc[i][j], x.x, w[j].x);
                        ffma2(acc[i][j], x.y, w[j].y);
                    }
                }
            }
            int cur = dstSh[eg * 8];
            float s4[4] = {0.f, 0.f, 0.f, 0.f};
            #pragma unroll
            for (int i = 0; i < 8; i++) {
                const int ee = eg * 8 + i;
                int dd2 = dstSh[ee];
                if (dd2 != cur) {
                    #pragma unroll
                    for (int j = 0; j < 4; j++)
                        atomicAdd(&g_sagg[cur * SD + oc + 32 * j], s4[j]);
                    cur = dd2;
                    s4[0] = s4[1] = s4[2] = s4[3] = 0.f;
                }
                float c = CS[ee];
                #pragma unroll
                for (int j = 0; j < 4; j++) s4[j] += f2x_sum(acc[i][j]) * c;
            }
            #pragma unroll
            for (int j = 0; j < 4; j++)
                atomicAdd(&g_sagg[cur * SD + oc + 32 * j], s4[j]);
        }

        // ---- vector gates -> Vm ----
        if (tid < TE) {
            const int ee = tid;
            const int epos = base + ee;
            float a6[6];
            #pragma unroll
            for (int j = 0; j < 6; j++) a6[j] = b3s[128 + j];
            #pragma unroll 8
            for (int k = 0; k < 64; k++) {
                float x = H2e[ee * 68 + k];
                #pragma unroll
                for (int j = 0; j < 6; j++) a6[j] += x * W3t[(128 + j) * 68 + k];
            }
            const float c = CS[ee];
            const int src = srcSh[ee];
            float rv[3];
            #pragma unroll
            for (int x = 0; x < 3; x++) rv[x] = (epos < EE) ? g_rs[epos * 3 + x] : 0.0f;
            #pragma unroll
            for (int vi = 0; vi < 3; vi++) {
                const float gv = a6[vi], gr = a6[3 + vi];
                #pragma unroll
                for (int x = 0; x < 3; x++)
                    Vm[ee * 12 + vi * 3 + x] =
                        (g_vbuf[src * 9 + vi * 3 + x] * gv + rv[x] * gr) * c;
            }
        }
        __syncthreads();

        // ---- group-reduce Vm -> v_agg ----
        if (tid < 36) {
            const int col = tid % 9, seg = tid / 9;
            const int e0 = seg * 16;
            int cur = dstSh[e0];
            float sum = 0.0f;
            #pragma unroll 4
            for (int i = 0; i < 16; i++) {
                int ee = e0 + i;
                int dd2 = dstSh[ee];
                if (dd2 != cur) {
                    atomicAdd(&g_vagg[cur * 9 + col], sum);
                    cur = dd2; sum = 0.0f;
                }
                sum += Vm[ee * 12 + col];
            }
            atomicAdd(&g_vagg[cur * 9 + col], sum);
        }
        __syncthreads();
    }
}

// ---------------- node kernel (f32x2, fused v update) ----------------
#define N_W1T 0
#define N_W2T (N_W1T + 64 * 260)
#define N_B1  (N_W2T + 128 * 68)
#define N_B2  (N_B1 + 64)
#define N_XT  (N_B2 + 128)
#define N_UT  (N_XT + 64 * 260)
#define N_TOT (N_UT + 64 * 68)

__global__ void __launch_bounds__(256, 1) k_node(
    const float* __restrict__ Wn1, const float* __restrict__ bn1,
    const float* __restrict__ Wn2, const float* __restrict__ bn2)
{
    extern __shared__ float sm[];
    float* W1t = sm + N_W1T;
    float* W2t = sm + N_W2T;
    float* b1s = sm + N_B1;
    float* b2s = sm + N_B2;
    float* Xt  = sm + N_XT;
    float* Ut  = sm + N_UT;

    const int tid = threadIdx.x;
    for (int i = tid; i < 64 * 256; i += 256) {
        int k = i >> 6, o = i & 63;
        W1t[o * 260 + k] = Wn1[k * 64 + o];
    }
    for (int i = tid; i < 128 * 64; i += 256) {
        int k = i >> 7, o = i & 127;
        W2t[o * 68 + k] = Wn2[k * 128 + o];
    }
    if (tid < 64) b1s[tid] = bn1[tid];
    if (tid < 128) b2s[tid] = bn2[tid];
    __syncthreads();

    const int wid = tid >> 5, lane = tid & 31;

    for (int tile = blockIdx.x; tile < NT_N; tile += gridDim.x) {
        const int base = tile * TN;
        const int nNd = min(TN, NN - base);

        for (int ii = wid; ii < TN; ii += 8) {
            const int n = base + ii;
            const bool valid = (ii < nNd);
            const float4* sp = (const float4*)&g_sbuf[(valid ? n : 0) * SD];
            float4* ap = (float4*)&g_sagg[(valid ? n : 0) * SD];
            float4 xs = sp[lane];
            float4 xa = ap[lane];
            if (!valid) { xs = make_float4(0,0,0,0); xa = xs; }
            *(float4*)(Xt + ii * 260 + lane * 4) = xs;
            *(float4*)(Xt + ii * 260 + 128 + lane * 4) = xa;
            if (valid) ap[lane] = make_float4(0, 0, 0, 0);
        }

        // fused v update for this node tile (independent of GEMMs)
        for (int idx = tid; idx < TN * 9; idx += 256) {
            const int nn = base + idx / 9;
            if (idx / 9 < nNd) {
                const int col = idx % 9;
                float va = g_vagg[nn * 9 + col];
                g_vbuf[nn * 9 + col] += va * g_icnt[nn];
                g_vagg[nn * 9 + col] = 0.0f;
            }
        }
        __syncthreads();

        // GEMM1: Ut = silu([s, s_agg] @ Wn1 + bn1)
        {
            const int oc = tid & 15;
            const int eg = tid >> 4;
            unsigned long long acc[4][4];
            #pragma unroll
            for (int i = 0; i < 4; i++)
                #pragma unroll
                for (int j = 0; j < 4; j++) acc[i][j] = packlo(b1s[oc + 16 * j]);
            #pragma unroll 2
            for (int k = 0; k < 256; k += 4) {
                ulonglong2 w[4];
                #pragma unroll
                for (int j = 0; j < 4; j++)
                    w[j] = *(const ulonglong2*)(W1t + (oc + 16 * j) * 260 + k);
                #pragma unroll
                for (int i = 0; i < 4; i++) {
                    ulonglong2 x = *(const ulonglong2*)(Xt + (eg * 4 + i) * 260 + k);
                    #pragma unroll
                    for (int j = 0; j < 4; j++) {
                        ffma2(acc[i][j], x.x, w[j].x);
                        ffma2(acc[i][j], x.y, w[j].y);
                    }
                }
            }
            #pragma unroll
            for (int i = 0; i < 4; i++)
                #pragma unroll
                for (int j = 0; j < 4; j++)
                    Ut[(eg * 4 + i) * 68 + oc + 16 * j] = silu_f(f2x_sum(acc[i][j]));
        }
        __syncthreads();

        // GEMM2: s += Ut @ Wn2 + bn2
        {
            const int oc = tid & 31;
            const int eg = tid >> 5;
            unsigned long long acc[8][4];
            #pragma unroll
            for (int i = 0; i < 8; i++)
                #pragma unroll
                for (int j = 0; j < 4; j++) acc[i][j] = packlo(b2s[oc + 32 * j]);
            #pragma unroll 4
            for (int k = 0; k < 64; k += 4) {
                ulonglong2 w[4];
                #pragma unroll
                for (int j = 0; j < 4; j++)
                    w[j] = *(const ulonglong2*)(W2t + (oc + 32 * j) * 68 + k);
                #pragma unroll
                for (int i = 0; i < 8; i++) {
                    ulonglong2 x = *(const ulonglong2*)(Ut + (eg * 8 + i) * 68 + k);
                    #pragma unroll
                    for (int j = 0; j < 4; j++) {
                        ffma2(acc[i][j], x.x, w[j].x);
                        ffma2(acc[i][j], x.y, w[j].y);
                    }
                }
            }
            #pragma unroll
            for (int i = 0; i < 8; i++) {
                const int n = base + eg * 8 + i;
                if (eg * 8 + i < nNd) {
                    #pragma unroll
                    for (int j = 0; j < 4; j++)
                        g_sbuf[n * SD + oc + 32 * j] += f2x_sum(acc[i][j]);
                }
            }
        }
        __syncthreads();
    }
}

// ---------------- host launch ----------------
extern "C" void kernel_launch(void* const* d_in, const int* in_sizes, int n_in,
                              void* d_out, int out_size) {
    const float* s   = (const float*)d_in[0];
    const float* v   = (const float*)d_in[1];
    const int*   ei  = (const int*)d_in[2];
    const float* d   = (const float*)d_in[3];
    const float* r   = (const float*)d_in[4];
    const float* W1  = (const float*)d_in[5];
    const float* b1  = (const float*)d_in[6];
    const float* W2  = (const float*)d_in[7];
    const float* b2  = (const float*)d_in[8];
    const float* W3  = (const float*)d_in[9];
    const float* b3  = (const float*)d_in[10];
    const float* Wn1 = (const float*)d_in[11];
    const float* bn1 = (const float*)d_in[12];
    const float* Wn2 = (const float*)d_in[13];
    const float* bn2 = (const float*)d_in[14];
    float* out = (float*)d_out;

    const int psm = P_TOT * 4;
    const int esm = E_TOT * 4;
    const int nsm = N_TOT * 4;
    cudaFuncSetAttribute(k_proj, cudaFuncAttributeMaxDynamicSharedMemorySize, psm);
    cudaFuncSetAttribute(k_edge, cudaFuncAttributeMaxDynamicSharedMemorySize, esm);
    cudaFuncSetAttribute(k_node, cudaFuncAttributeMaxDynamicSharedMemorySize, nsm);

    k_init<<<1024, 256>>>(s, v);
    k_cnt<<<(EE + 255) / 256, 256>>>(ei);
    k_scan<<<1, 1024>>>();
    k_perm<<<(EE + 255) / 256, 256>>>(ei, d, r);
    k_zero<<<1024, 256>>>();

    for (int l = 0; l < DEPTH; l++) {
        k_proj<<<NT_N, 256, psm>>>(W1 + l * 257 * 64);
        k_edge<<<304, 256, esm>>>(W1 + l * 257 * 64, b1 + l * 64,
                                  W2 + l * 64 * 64, b2 + l * 64,
                                  W3 + l * 64 * 134, b3 + l * 134);
        k_node<<<152, 256, nsm>>>(Wn1 + l * 256 * 64, bn1 + l * 64,
                                  Wn2 + l * 64 * 128, bn2 + l * 128);
    }
    k_out<<<1024, 256>>>(out);
}